// round 6
// baseline (speedup 1.0000x reference)
#include <cuda_runtime.h>
#include <cstddef>
#include <cstdint>

// ---------------------------------------------------------------------------
// Collapsed model (only pyramid level L-1 survives the reference):
//   g[b,f]    = (1/256) * sum over 16x16 patch grid of x   (f = c*256+pi*16+pj)
//   root[b,d] = sum_f W_emb[d,f]*g[b,f] + b_emb[d] + pos4[d]
//   out[b,o]  = sum_d W_cls[o,d]*root[b,d] + b_cls[o]
// ---------------------------------------------------------------------------

__device__ float g_scratch[64 * 768];      // 196 KB
__device__ float root_scratch[64 * 128];   // 32 KB

__device__ __forceinline__ uint32_t smem_u32(const void* p) {
    return (uint32_t)__cvta_generic_to_shared(p);
}
__device__ __forceinline__ void cp_async16(uint32_t dst, const void* src) {
    asm volatile("cp.async.cg.shared.global [%0], [%1], 16;" :: "r"(dst), "l"(src));
}
__device__ __forceinline__ void cp_async_wait_all() {
    asm volatile("cp.async.commit_group;\n\tcp.async.wait_group 0;" ::: "memory");
}

// ---------------------------------------------------------------------------
// Kernel 1: strided pooling of x via cp.async (deep MLP without registers).
// grid (8 pi-pairs, 3 channels, 64 batch) = 1536 blocks of 128 threads.
// Thread (rbase=t>>6, c4=t&63) owns row pi = 2q+rbase, float4-column c4:
// issues 16 cp.async.cg (16B each) into smem, waits, sums its 16 float4s,
// reduces over bw with butterfly shuffles + tiny smem exchange.
// smem 32KB+ -> 6 blocks/SM co-resident -> ~190KB of loads in flight per SM.
// ---------------------------------------------------------------------------
__global__ __launch_bounds__(128) void k1_pool(const float* __restrict__ x) {
    const int q = blockIdx.x;    // 0..7 pi pair
    const int c = blockIdx.y;    // 0..2 channel
    const int b = blockIdx.z;    // 0..63 batch
    const int t = threadIdx.x;
    const int rbase = t >> 6;    // 0..1
    const int c4 = t & 63;       // float4 column 0..63
    const int pi = q * 2 + rbase;

    __shared__ float4 buf[16 * 2 * 64];   // [m][rbase][c4], 32 KB
    __shared__ float4 spart[4][4];        // per-warp quad partials

    const float4* plane =
        reinterpret_cast<const float4*>(x + ((size_t)(b * 3 + c) << 16));

    // 16 outstanding 16B async copies per thread.
#pragma unroll
    for (int m = 0; m < 16; m++) {
        uint32_t dst = smem_u32(&buf[(m * 2 + rbase) * 64 + c4]);
        cp_async16(dst, &plane[(pi + 16 * m) * 64 + c4]);
    }
    cp_async_wait_all();

    // Sum over bh (each thread reads back only what it wrote; no barrier).
    float4 acc = make_float4(0.f, 0.f, 0.f, 0.f);
#pragma unroll
    for (int m = 0; m < 16; m++) {
        float4 v = buf[(m * 2 + rbase) * 64 + c4];
        acc.x += v.x; acc.y += v.y; acc.z += v.z; acc.w += v.w;
    }

    // Reduce over bw within warp: lanes with equal (c4&3) differ in c4>>2.
#pragma unroll
    for (int off = 4; off <= 16; off <<= 1) {
        acc.x += __shfl_xor_sync(0xffffffffu, acc.x, off);
        acc.y += __shfl_xor_sync(0xffffffffu, acc.y, off);
        acc.z += __shfl_xor_sync(0xffffffffu, acc.z, off);
        acc.w += __shfl_xor_sync(0xffffffffu, acc.w, off);
    }
    if ((t & 31) < 4) spart[t >> 5][t & 3] = acc;
    __syncthreads();

    if (t < 8) {
        const int rb = t >> 2;   // 0..1  (row within pair)
        const int qq = t & 3;    // pj quad
        float4 r0 = spart[rb * 2 + 0][qq];
        float4 r1 = spart[rb * 2 + 1][qq];
        const float sc = 1.0f / 256.0f;
        float4 out = make_float4((r0.x + r1.x) * sc, (r0.y + r1.y) * sc,
                                 (r0.z + r1.z) * sc, (r0.w + r1.w) * sc);
        reinterpret_cast<float4*>(
            g_scratch + b * 768 + c * 256 + (q * 2 + rb) * 16)[qq] = out;
    }
}

// ---------------------------------------------------------------------------
// Kernel 2 (R1 version): root = g @ W_emb^T + (b_emb + pos4).
// grid (8 d-tiles, 16 b-tiles), 128 threads.  Warp does 4 d's, k=768 over
// lanes (24 g regs per batch, 4 batches), shfl-reduce.
// ---------------------------------------------------------------------------
__global__ __launch_bounds__(128) void k2_root(const float* __restrict__ W_emb,
                                               const float* __restrict__ b_emb,
                                               const float* __restrict__ pos4) {
    const int dt = blockIdx.x;   // 0..7
    const int bt = blockIdx.y;   // 0..15
    const int t = threadIdx.x;
    const int wid = t >> 5;
    const int lane = t & 31;

    float greg[4][24];
#pragma unroll
    for (int j = 0; j < 4; j++) {
        const float* gp = g_scratch + (bt * 4 + j) * 768 + lane;
#pragma unroll
        for (int i = 0; i < 24; i++) greg[j][i] = gp[i * 32];
    }

#pragma unroll
    for (int dd = 0; dd < 4; dd++) {
        const int d = dt * 16 + wid * 4 + dd;
        const float* wp = W_emb + d * 768 + lane;
        float a0 = 0.f, a1 = 0.f, a2 = 0.f, a3 = 0.f;
#pragma unroll
        for (int i = 0; i < 24; i++) {
            float w = wp[i * 32];
            a0 += w * greg[0][i];
            a1 += w * greg[1][i];
            a2 += w * greg[2][i];
            a3 += w * greg[3][i];
        }
#pragma unroll
        for (int off = 16; off >= 1; off >>= 1) {
            a0 += __shfl_xor_sync(0xffffffffu, a0, off);
            a1 += __shfl_xor_sync(0xffffffffu, a1, off);
            a2 += __shfl_xor_sync(0xffffffffu, a2, off);
            a3 += __shfl_xor_sync(0xffffffffu, a3, off);
        }
        if (lane == 0) {
            const float bias = b_emb[d] + pos4[d];
            root_scratch[(bt * 4 + 0) * 128 + d] = a0 + bias;
            root_scratch[(bt * 4 + 1) * 128 + d] = a1 + bias;
            root_scratch[(bt * 4 + 2) * 128 + d] = a2 + bias;
            root_scratch[(bt * 4 + 3) * 128 + d] = a3 + bias;
        }
    }
}

// ---------------------------------------------------------------------------
// Kernel 3 (R1 version): out = root @ W_cls^T + b_cls.
// grid (32 o-tiles, 8 b-tiles), 128 threads.
// ---------------------------------------------------------------------------
__global__ __launch_bounds__(128) void k3_logits(const float* __restrict__ W_cls,
                                                 const float* __restrict__ b_cls,
                                                 float* __restrict__ out) {
    const int ot = blockIdx.x;   // 0..31
    const int bt = blockIdx.y;   // 0..7
    const int t = threadIdx.x;
    const int wid = t >> 5;
    const int lane = t & 31;

    float rreg[8][4];
#pragma unroll
    for (int j = 0; j < 8; j++) {
        const float* rp = root_scratch + (bt * 8 + j) * 128 + lane;
#pragma unroll
        for (int i = 0; i < 4; i++) rreg[j][i] = rp[i * 32];
    }

#pragma unroll
    for (int oo = 0; oo < 8; oo++) {
        const int o = ot * 32 + wid * 8 + oo;
        if (o < 1000) {
            const float* wp = W_cls + o * 128 + lane;
            float acc[8];
#pragma unroll
            for (int j = 0; j < 8; j++) acc[j] = 0.f;
#pragma unroll
            for (int i = 0; i < 4; i++) {
                float w = wp[i * 32];
#pragma unroll
                for (int j = 0; j < 8; j++) acc[j] += w * rreg[j][i];
            }
#pragma unroll
            for (int off = 16; off >= 1; off >>= 1) {
#pragma unroll
                for (int j = 0; j < 8; j++)
                    acc[j] += __shfl_xor_sync(0xffffffffu, acc[j], off);
            }
            if (lane == 0) {
                const float bc = b_cls[o];
#pragma unroll
                for (int j = 0; j < 8; j++)
                    out[(bt * 8 + j) * 1000 + o] = acc[j] + bc;
            }
        }
    }
}

// ---------------------------------------------------------------------------
// Inputs (metadata order): 0:x 1:W_emb 2:b_emb 3:pos0 4:pos1 5:pos2 6:pos3
//                          7:pos4 8:W_cls 9:b_cls.  Output: (64,1000) f32.
// ---------------------------------------------------------------------------
extern "C" void kernel_launch(void* const* d_in, const int* in_sizes, int n_in,
                              void* d_out, int out_size) {
    const float* x     = (const float*)d_in[0];
    const float* W_emb = (const float*)d_in[1];
    const float* b_emb = (const float*)d_in[2];
    const float* pos4  = (const float*)d_in[7];
    const float* W_cls = (const float*)d_in[8];
    const float* b_cls = (const float*)d_in[9];
    float* out = (float*)d_out;

    k1_pool<<<dim3(8, 3, 64), 128>>>(x);
    k2_root<<<dim3(8, 16), 128>>>(W_emb, b_emb, pos4);
    k3_logits<<<dim3(32, 8), 128>>>(W_cls, b_cls, out);
}

// round 7
// speedup vs baseline: 1.0037x; 1.0037x over previous
#include <cuda_runtime.h>
#include <cstddef>

// ---------------------------------------------------------------------------
// Collapsed model (only pyramid level L-1 survives the reference):
//   g[b,f]    = (1/256) * sum over 16x16 patch grid of x   (f = c*256+pi*16+pj)
//   root[b,d] = sum_f W_emb[d,f]*g[b,f] + b_emb[d] + pos4[d]
//   out[b,o]  = sum_d W_cls[o,d]*root[b,d] + b_cls[o]
// ---------------------------------------------------------------------------

__device__ float g_scratch[64 * 768];      // 196 KB ([b][c][pi][pj] = [p][256])
__device__ float root_scratch[64 * 128];   // 32 KB

// ---------------------------------------------------------------------------
// Kernel 1: strided pooling of x with a PER-BLOCK SEQUENTIAL DRAM stream.
// One block per (b,c) plane: 192 blocks x 512 threads.  The block sweeps its
// 256KB plane front-to-back (each wavefront = 8KB contiguous), so DRAM sees
// ~192 tight sequential streams (row-buffer friendly) instead of ~30k
// scattered 1KB rows.  Thread t at step k reads float4 slot t+512k:
//   row = (t>>6) + 8k,  pi = (t>>6) + 8*(k&1)  -> 2 accumulators.
// Reduce over bw via butterfly shuffles + 2KB smem exchange.
// ---------------------------------------------------------------------------
__global__ __launch_bounds__(512) void k1_pool(const float* __restrict__ x) {
    const int p = blockIdx.x;        // plane = b*3+c, 0..191
    const int t = threadIdx.x;       // 0..511
    const int base = t >> 6;         // 0..7  (row low bits)
    const int c4 = t & 63;           // float4 column 0..63
    const int w = t >> 5;            // warp 0..15

    const float4* plane = reinterpret_cast<const float4*>(x + ((size_t)p << 16));

    float4 a0 = make_float4(0.f, 0.f, 0.f, 0.f);   // pi = base
    float4 a1 = a0;                                // pi = base + 8
#pragma unroll
    for (int k = 0; k < 32; k += 2) {
        float4 v0 = plane[t + 512 * k];
        float4 v1 = plane[t + 512 * (k + 1)];
        a0.x += v0.x; a0.y += v0.y; a0.z += v0.z; a0.w += v0.w;
        a1.x += v1.x; a1.y += v1.y; a1.z += v1.z; a1.w += v1.w;
    }

    // Reduce over bw bits inside the warp: lanes with equal (c4&3) differ in
    // c4 bits 2..4 (offsets 4,8,16).  c4 bit 5 = warp parity, via smem.
#pragma unroll
    for (int off = 4; off <= 16; off <<= 1) {
        a0.x += __shfl_xor_sync(0xffffffffu, a0.x, off);
        a0.y += __shfl_xor_sync(0xffffffffu, a0.y, off);
        a0.z += __shfl_xor_sync(0xffffffffu, a0.z, off);
        a0.w += __shfl_xor_sync(0xffffffffu, a0.w, off);
        a1.x += __shfl_xor_sync(0xffffffffu, a1.x, off);
        a1.y += __shfl_xor_sync(0xffffffffu, a1.y, off);
        a1.z += __shfl_xor_sync(0xffffffffu, a1.z, off);
        a1.w += __shfl_xor_sync(0xffffffffu, a1.w, off);
    }

    __shared__ float4 spart[16][2][4];   // [warp][j][pj-quad], 2 KB
    if ((t & 31) < 4) {
        spart[w][0][t & 3] = a0;
        spart[w][1][t & 3] = a1;
    }
    __syncthreads();

    // Finalize: thread t<64 -> pi = t>>2, quad qq = t&3.
    // Contributing warps: w = 2*(pi&7) and w+1 (the two c4 halves), j = pi>>3.
    if (t < 64) {
        const int pi = t >> 2;
        const int qq = t & 3;
        const int bw2 = (pi & 7) * 2;
        const int j = pi >> 3;
        float4 r0 = spart[bw2 + 0][j][qq];
        float4 r1 = spart[bw2 + 1][j][qq];
        const float sc = 1.0f / 256.0f;
        float4 out = make_float4((r0.x + r1.x) * sc, (r0.y + r1.y) * sc,
                                 (r0.z + r1.z) * sc, (r0.w + r1.w) * sc);
        reinterpret_cast<float4*>(g_scratch + p * 256 + pi * 16)[qq] = out;
    }
}

// ---------------------------------------------------------------------------
// Kernel 2 (R1 version): root = g @ W_emb^T + (b_emb + pos4).
// grid (8 d-tiles, 16 b-tiles), 128 threads.  Warp does 4 d's, k=768 over
// lanes (24 g regs per batch, 4 batches), shfl-reduce.
// ---------------------------------------------------------------------------
__global__ __launch_bounds__(128) void k2_root(const float* __restrict__ W_emb,
                                               const float* __restrict__ b_emb,
                                               const float* __restrict__ pos4) {
    const int dt = blockIdx.x;   // 0..7
    const int bt = blockIdx.y;   // 0..15
    const int t = threadIdx.x;
    const int wid = t >> 5;
    const int lane = t & 31;

    float greg[4][24];
#pragma unroll
    for (int j = 0; j < 4; j++) {
        const float* gp = g_scratch + (bt * 4 + j) * 768 + lane;
#pragma unroll
        for (int i = 0; i < 24; i++) greg[j][i] = gp[i * 32];
    }

#pragma unroll
    for (int dd = 0; dd < 4; dd++) {
        const int d = dt * 16 + wid * 4 + dd;
        const float* wp = W_emb + d * 768 + lane;
        float a0 = 0.f, a1 = 0.f, a2 = 0.f, a3 = 0.f;
#pragma unroll
        for (int i = 0; i < 24; i++) {
            float w = wp[i * 32];
            a0 += w * greg[0][i];
            a1 += w * greg[1][i];
            a2 += w * greg[2][i];
            a3 += w * greg[3][i];
        }
#pragma unroll
        for (int off = 16; off >= 1; off >>= 1) {
            a0 += __shfl_xor_sync(0xffffffffu, a0, off);
            a1 += __shfl_xor_sync(0xffffffffu, a1, off);
            a2 += __shfl_xor_sync(0xffffffffu, a2, off);
            a3 += __shfl_xor_sync(0xffffffffu, a3, off);
        }
        if (lane == 0) {
            const float bias = b_emb[d] + pos4[d];
            root_scratch[(bt * 4 + 0) * 128 + d] = a0 + bias;
            root_scratch[(bt * 4 + 1) * 128 + d] = a1 + bias;
            root_scratch[(bt * 4 + 2) * 128 + d] = a2 + bias;
            root_scratch[(bt * 4 + 3) * 128 + d] = a3 + bias;
        }
    }
}

// ---------------------------------------------------------------------------
// Kernel 3 (R1 version): out = root @ W_cls^T + b_cls.
// grid (32 o-tiles, 8 b-tiles), 128 threads.
// ---------------------------------------------------------------------------
__global__ __launch_bounds__(128) void k3_logits(const float* __restrict__ W_cls,
                                                 const float* __restrict__ b_cls,
                                                 float* __restrict__ out) {
    const int ot = blockIdx.x;   // 0..31
    const int bt = blockIdx.y;   // 0..7
    const int t = threadIdx.x;
    const int wid = t >> 5;
    const int lane = t & 31;

    float rreg[8][4];
#pragma unroll
    for (int j = 0; j < 8; j++) {
        const float* rp = root_scratch + (bt * 8 + j) * 128 + lane;
#pragma unroll
        for (int i = 0; i < 4; i++) rreg[j][i] = rp[i * 32];
    }

#pragma unroll
    for (int oo = 0; oo < 8; oo++) {
        const int o = ot * 32 + wid * 8 + oo;
        if (o < 1000) {
            const float* wp = W_cls + o * 128 + lane;
            float acc[8];
#pragma unroll
            for (int j = 0; j < 8; j++) acc[j] = 0.f;
#pragma unroll
            for (int i = 0; i < 4; i++) {
                float w = wp[i * 32];
#pragma unroll
                for (int j = 0; j < 8; j++) acc[j] += w * rreg[j][i];
            }
#pragma unroll
            for (int off = 16; off >= 1; off >>= 1) {
#pragma unroll
                for (int j = 0; j < 8; j++)
                    acc[j] += __shfl_xor_sync(0xffffffffu, acc[j], off);
            }
            if (lane == 0) {
                const float bc = b_cls[o];
#pragma unroll
                for (int j = 0; j < 8; j++)
                    out[(bt * 8 + j) * 1000 + o] = acc[j] + bc;
            }
        }
    }
}

// ---------------------------------------------------------------------------
// Inputs (metadata order): 0:x 1:W_emb 2:b_emb 3:pos0 4:pos1 5:pos2 6:pos3
//                          7:pos4 8:W_cls 9:b_cls.  Output: (64,1000) f32.
// ---------------------------------------------------------------------------
extern "C" void kernel_launch(void* const* d_in, const int* in_sizes, int n_in,
                              void* d_out, int out_size) {
    const float* x     = (const float*)d_in[0];
    const float* W_emb = (const float*)d_in[1];
    const float* b_emb = (const float*)d_in[2];
    const float* pos4  = (const float*)d_in[7];
    const float* W_cls = (const float*)d_in[8];
    const float* b_cls = (const float*)d_in[9];
    float* out = (float*)d_out;

    k1_pool<<<192, 512>>>(x);
    k2_root<<<dim3(8, 16), 128>>>(W_emb, b_emb, pos4);
    k3_logits<<<dim3(32, 8), 128>>>(W_cls, b_cls, out);
}